// round 9
// baseline (speedup 1.0000x reference)
#include <cuda_runtime.h>
#include <cstdint>

// ResidualGraphConv: out = concat( gconv(adj,x,W1)+b1 , relu(gconv(adj,x,W2)+b2) )
// gconv(adj,x,W) = sum_d W[d] @ (x @ adj^d)
//
// Horner over combined channels Wc[d] = [W1[d]; W2[d]] (64 out-channels):
//   V = U3;  V = V*A + U2;  V = V*A + U1;  V = V*A + U0   (U_d = Wc[d] @ x)
// Final step adds bias and relus the upper half, writing d_out [16,64,2048] f32.
//
// GEMM per step per batch: C[64,2048] = V[64,2048] * A[2048,2048] (+ Wc[d]@x fused
// as two extra K=32 chunks). mma.sync.m16n8k8 tf32 with RNA rounding at SMEM store.

#define BATCH 16
#define CCH   64
#define NN    2048
#define NT    128
#define KB    32
#define LDA   36    // As[64][36]  -> fragment banks 4g+t(+kb) all distinct
#define LDB   136   // Bs[32][136] -> fragment banks 8t+mf+g all distinct

__device__ float g_V0[BATCH * CCH * NN];
__device__ float g_V1[BATCH * CCH * NN];

__device__ __forceinline__ float ftf32(float v) {
    uint32_t u;
    asm("cvt.rna.tf32.f32 %0, %1;" : "=r"(u) : "f"(v));
    return __uint_as_float(u);
}
__device__ __forceinline__ float4 ftf32x4(float4 v) {
    v.x = ftf32(v.x); v.y = ftf32(v.y); v.z = ftf32(v.z); v.w = ftf32(v.w);
    return v;
}

__device__ __forceinline__ void mma_tf32(float* c,
                                         uint32_t a0, uint32_t a1, uint32_t a2, uint32_t a3,
                                         uint32_t b0, uint32_t b1) {
    asm volatile(
        "mma.sync.aligned.m16n8k8.row.col.f32.tf32.tf32.f32 "
        "{%0,%1,%2,%3}, {%4,%5,%6,%7}, {%8,%9}, {%0,%1,%2,%3};\n"
        : "+f"(c[0]), "+f"(c[1]), "+f"(c[2]), "+f"(c[3])
        : "r"(a0), "r"(a1), "r"(a2), "r"(a3), "r"(b0), "r"(b1));
}

// vin_sel: 0 -> g_V0, 1 -> g_V1 (ignored when nk_main==0)
// vout_sel: 0 -> g_V0, 1 -> g_V1, 2 -> dout with bias+relu epilogue
__global__ void __launch_bounds__(256, 2)
horner_kernel(const float* __restrict__ adj,
              const float* __restrict__ x,
              const float* __restrict__ W1,
              const float* __restrict__ W2,
              const float* __restrict__ bias1,
              const float* __restrict__ bias2,
              float* __restrict__ dout,
              int nk_main, int deg, int vin_sel, int vout_sel) {
    __shared__ float As[CCH * LDA];   //  9216 B
    __shared__ float Bs[KB * LDB];    // 17408 B

    const int tid  = threadIdx.x;
    const int lane = tid & 31;
    const int wid  = tid >> 5;
    const int wm   = wid & 3;          // warp row (16 channels each)
    const int wn   = wid >> 2;         // warp col (64 cols each)
    const int g    = lane >> 2;        // groupID
    const int t    = lane & 3;         // threadID_in_group
    const int b    = blockIdx.y;
    const int m0   = blockIdx.x * NT;

    const float* Vin  = vin_sel ? g_V1 : g_V0;
    float*       Vout = (vout_sel == 0) ? g_V0 : ((vout_sel == 1) ? g_V1 : dout);

    // staging index precompute
    const int arow = tid >> 3;         // + 32*i -> A rows 0..63
    const int aq   = tid & 7;          // float4 index within 32-wide k row
    const int brow = tid >> 5;         // + 8*i  -> B rows 0..31
    const int bq   = tid & 31;         // float4 index within 128-wide m row

    const int nchunks = nk_main + 2;   // 2 trailing chunks = fused Wc[deg] @ x

    float acc[8][4];
#pragma unroll
    for (int j = 0; j < 8; j++)
#pragma unroll
        for (int i = 0; i < 4; i++) acc[j][i] = 0.0f;

    float4 areg[2], breg[4];

    // ---- load chunk cc into registers (global -> reg) ----
    auto load_chunk = [&](int cc) {
        const bool isU = (cc >= nk_main);
        const int  k0  = cc * KB;
        const int  ci0 = (cc - nk_main) * KB;
#pragma unroll
        for (int i = 0; i < 2; i++) {
            int r = arow + 32 * i;
            const float* p;
            if (!isU) {
                p = Vin + ((b << 6) + r) * NN + k0 + (aq << 2);
            } else {
                const float* W = (r < 32) ? W1 : W2;
                int rr = r & 31;
                p = W + ((deg * 32 + rr) << 6) + ci0 + (aq << 2);
            }
            areg[i] = *reinterpret_cast<const float4*>(p);
        }
#pragma unroll
        for (int i = 0; i < 4; i++) {
            int r = brow + 8 * i;
            const float* p;
            if (!isU) {
                p = adj + (size_t)(b * NN + k0 + r) * NN + m0 + (bq << 2);
            } else {
                p = x + ((b << 6) + ci0 + r) * NN + m0 + (bq << 2);
            }
            breg[i] = *reinterpret_cast<const float4*>(p);
        }
    };

    load_chunk(0);

    for (int cc = 0; cc < nchunks; cc++) {
        __syncthreads();   // previous compute done before overwriting SMEM
        // reg -> SMEM with tf32 rounding (RNA, unbiased)
#pragma unroll
        for (int i = 0; i < 2; i++) {
            int r = arow + 32 * i;
            *reinterpret_cast<float4*>(&As[r * LDA + (aq << 2)]) = ftf32x4(areg[i]);
        }
#pragma unroll
        for (int i = 0; i < 4; i++) {
            int r = brow + 8 * i;
            *reinterpret_cast<float4*>(&Bs[r * LDB + (bq << 2)]) = ftf32x4(breg[i]);
        }
        __syncthreads();

        if (cc + 1 < nchunks) load_chunk(cc + 1);  // overlap next loads with compute

        const int r0 = wm * 16 + g;
#pragma unroll
        for (int kk4 = 0; kk4 < 4; kk4++) {
            const int kb = kk4 * 8;
            uint32_t a0 = __float_as_uint(As[r0 * LDA + kb + t]);
            uint32_t a1 = __float_as_uint(As[(r0 + 8) * LDA + kb + t]);
            uint32_t a2 = __float_as_uint(As[r0 * LDA + kb + t + 4]);
            uint32_t a3 = __float_as_uint(As[(r0 + 8) * LDA + kb + t + 4]);
#pragma unroll
            for (int j = 0; j < 8; j++) {
                const int mf = wn * 64 + j * 8;
                uint32_t b0 = __float_as_uint(Bs[(kb + t) * LDB + mf + g]);
                uint32_t b1 = __float_as_uint(Bs[(kb + t + 4) * LDB + mf + g]);
                mma_tf32(acc[j], a0, a1, a2, a3, b0, b1);
            }
        }
    }

    // ---- epilogue ----
    const int r0 = wm * 16 + g;
    const int r1 = r0 + 8;
    float add0 = 0.0f, add1 = 0.0f;
    bool relu0 = false, relu1 = false;
    if (vout_sel == 2) {
        add0 = (r0 < 32) ? bias1[r0] : bias2[r0 - 32];
        add1 = (r1 < 32) ? bias1[r1] : bias2[r1 - 32];
        relu0 = (r0 >= 32);
        relu1 = (r1 >= 32);
    }
#pragma unroll
    for (int j = 0; j < 8; j++) {
        const int m = m0 + wn * 64 + j * 8 + 2 * t;
        float v0 = acc[j][0], v1 = acc[j][1];   // row r0, cols m, m+1
        float v2 = acc[j][2], v3 = acc[j][3];   // row r1
        if (vout_sel == 2) {
            v0 += add0; v1 += add0;
            v2 += add1; v3 += add1;
            if (relu0) { v0 = fmaxf(v0, 0.0f); v1 = fmaxf(v1, 0.0f); }
            if (relu1) { v2 = fmaxf(v2, 0.0f); v3 = fmaxf(v3, 0.0f); }
        }
        *reinterpret_cast<float2*>(&Vout[((b << 6) + r0) * NN + m]) = make_float2(v0, v1);
        *reinterpret_cast<float2*>(&Vout[((b << 6) + r1) * NN + m]) = make_float2(v2, v3);
    }
}

extern "C" void kernel_launch(void* const* d_in, const int* in_sizes, int n_in,
                              void* d_out, int out_size) {
    (void)in_sizes; (void)n_in; (void)out_size;
    const float* adj = (const float*)d_in[0];   // [16,2048,2048]
    const float* x   = (const float*)d_in[1];   // [16,64,2048]
    const float* W1  = (const float*)d_in[2];   // [4,32,64]
    const float* b1  = (const float*)d_in[3];   // [32]
    const float* W2  = (const float*)d_in[4];   // [4,32,64]
    const float* b2  = (const float*)d_in[5];   // [32]
    float* out = (float*)d_out;                 // [16,64,2048]

    dim3 grid(NN / NT, BATCH);
    dim3 block(256);

    // V0 = U3 = Wc[3] @ x  (projection: zero main-K chunks, only the fused U chunks)
    horner_kernel<<<grid, block>>>(adj, x, W1, W2, b1, b2, out, 0, 3, 0, 0);
    // V1 = V0*A + U2
    horner_kernel<<<grid, block>>>(adj, x, W1, W2, b1, b2, out, NN / KB, 2, 0, 1);
    // V0 = V1*A + U1
    horner_kernel<<<grid, block>>>(adj, x, W1, W2, b1, b2, out, NN / KB, 1, 1, 0);
    // out = V0*A + U0 + bias, relu upper half
    horner_kernel<<<grid, block>>>(adj, x, W1, W2, b1, b2, out, NN / KB, 0, 0, 2);
}